// round 7
// baseline (speedup 1.0000x reference)
#include <cuda_runtime.h>
#include <cuda_bf16.h>
#include <cstdint>

// Problem constants: N=100000, E=800000, D=128, H=4, DH=32
#define MAX_N 100096
#define ND ((size_t)MAX_N * 128)

__device__ float g_Q[ND];
__device__ float g_K[ND];
__device__ float g_V[ND];
__device__ __nv_bfloat16 g_Yhi[ND], g_Ylo[ND];
__device__ __nv_bfloat16 g_Whi[4 * 16384], g_Wlo[4 * 16384];  // Wq,Wk,Wv,Wo(K-permuted)
__device__ int g_rowptr[MAX_N + 1];

#define LDROW 136      // bf16 elems per padded smem row (conflict-free ldmatrix)
#define A_ROWS 32

// qkv smem layout (bf16 elems): A hi | A lo | B hi | B lo   (single A buffer)
#define QKV_A_PART (A_ROWS * LDROW)              // 4352
#define QKV_B_HI   (2 * QKV_A_PART)              // 8704
#define QKV_B_LO   (QKV_B_HI + 128 * LDROW)
#define QKV_SMEM_BYTES ((QKV_B_LO + 128 * LDROW) * 2)   // 87040

// out smem layout: A double-buffered hi/lo | B hi | B lo
#define OUT_A_PART (A_ROWS * LDROW)
#define OUT_A_BUF  (2 * OUT_A_PART)
#define OUT_B_HI   (2 * OUT_A_BUF)
#define OUT_B_LO   (OUT_B_HI + 128 * LDROW)
#define OUT_SMEM_BYTES ((OUT_B_LO + 128 * LDROW) * 2)   // 104448

// ---------------------------------------------------------------------------
__device__ __forceinline__ uint32_t smem_u32(const void* p) {
    uint32_t a;
    asm("{ .reg .u64 t; cvta.to.shared.u64 t, %1; cvt.u32.u64 %0, t; }" : "=r"(a) : "l"(p));
    return a;
}
__device__ __forceinline__ void ldm_x4(uint32_t* r, uint32_t addr) {
    asm volatile("ldmatrix.sync.aligned.m8n8.x4.shared.b16 {%0,%1,%2,%3}, [%4];"
                 : "=r"(r[0]), "=r"(r[1]), "=r"(r[2]), "=r"(r[3]) : "r"(addr));
}
__device__ __forceinline__ void mma16816(float* d, const uint32_t* a, const uint32_t* b) {
    asm volatile(
        "mma.sync.aligned.m16n8k16.row.col.f32.bf16.bf16.f32 "
        "{%0,%1,%2,%3},{%4,%5,%6,%7},{%8,%9},{%0,%1,%2,%3};"
        : "+f"(d[0]), "+f"(d[1]), "+f"(d[2]), "+f"(d[3])
        : "r"(a[0]), "r"(a[1]), "r"(a[2]), "r"(a[3]), "r"(b[0]), "r"(b[1]));
}
__device__ __forceinline__ void cp16(uint32_t saddr, const void* gptr) {
    asm volatile("cp.async.ca.shared.global [%0], [%1], 16;" :: "r"(saddr), "l"(gptr));
}
#define CP_COMMIT() asm volatile("cp.async.commit_group;" ::: "memory")
#define CP_WAIT0()  asm volatile("cp.async.wait_group 0;" ::: "memory")

__device__ __forceinline__ void split4(float4 v, __nv_bfloat162* hi0, __nv_bfloat162* hi1,
                                       __nv_bfloat162* lo0, __nv_bfloat162* lo1) {
    __nv_bfloat16 h0 = __float2bfloat16_rn(v.x), h1 = __float2bfloat16_rn(v.y);
    __nv_bfloat16 h2 = __float2bfloat16_rn(v.z), h3 = __float2bfloat16_rn(v.w);
    hi0->x = h0; hi0->y = h1; hi1->x = h2; hi1->y = h3;
    lo0->x = __float2bfloat16_rn(v.x - __bfloat162float(h0));
    lo0->y = __float2bfloat16_rn(v.y - __bfloat162float(h1));
    lo1->x = __float2bfloat16_rn(v.z - __bfloat162float(h2));
    lo1->y = __float2bfloat16_rn(v.w - __bfloat162float(h3));
}

// ---------------------------------------------------------------------------
// Weight conversion only: {Wq,Wk,Wv,Wo(K-perm)} -> g_Whi/lo  (tiny kernel)
// ---------------------------------------------------------------------------
__global__ void convert_weights(const float* __restrict__ Wq, const float* __restrict__ Wk,
                                const float* __restrict__ Wv, const float* __restrict__ Wo)
{
    const int idx = blockIdx.x * blockDim.x + threadIdx.x;
    if (idx >= 4 * 16384) return;
    const int mat = idx >> 14, e = idx & 16383;
    const int f = e >> 7, k = e & 127;
    const float* W = (mat == 0) ? Wq : (mat == 1) ? Wk : (mat == 2) ? Wv : Wo;
    const int kk = (mat == 3) ? ((k & 31) * 4 + (k >> 5)) : k;  // undo head-major for Wo
    const float v = W[f * 128 + kk];
    __nv_bfloat16 h = __float2bfloat16_rn(v);
    g_Whi[idx] = h;
    g_Wlo[idx] = __float2bfloat16_rn(v - __bfloat162float(h));
}

// ---------------------------------------------------------------------------
// CSR rowptr from sorted row[]
// ---------------------------------------------------------------------------
__global__ void build_rowptr(const int* __restrict__ row, int E, int Nn)
{
    const int e = blockIdx.x * blockDim.x + threadIdx.x;
    if (e >= E) return;
    const int r = row[e];
    const int prev = (e == 0) ? -1 : row[e - 1];
    for (int j = prev + 1; j <= r; j++) g_rowptr[j] = e;
    if (e == E - 1)
        for (int j = r + 1; j <= Nn; j++) g_rowptr[j] = E;
}

// ---------------------------------------------------------------------------
// Warp-MMA tile: acc += Ahi*Bhi + Alo*Bhi + Ahi*Blo, K=128 resident.
// 8 warps: warp_m = w&1 (16 rows), warp_n = w>>1 (32 cols). Warp tile 16x32.
// ---------------------------------------------------------------------------
__device__ __forceinline__ void mma_tile(float acc[4][4],
                                         uint32_t AHI, uint32_t ALO,
                                         uint32_t BHI, uint32_t BLO,
                                         int warp_m, int warp_n, int lane)
{
    const uint32_t a_off = (uint32_t)((warp_m * 16 + (lane & 15)) * LDROW + ((lane >> 4) << 3)) * 2;
    const uint32_t b_off = (uint32_t)((warp_n * 32 + (lane & 7) + ((lane >> 4) << 3)) * LDROW +
                                      (lane & 8)) * 2;
    #pragma unroll
    for (int ks = 0; ks < 8; ks++) {
        const uint32_t kb = (uint32_t)ks * 32;   // 16 bf16 = 32 B
        uint32_t aH[4], aL[4], bH[2][4], bL[2][4];
        ldm_x4(aH, AHI + a_off + kb);
        #pragma unroll
        for (int g = 0; g < 2; g++)
            ldm_x4(bH[g], BHI + b_off + kb + (uint32_t)(g * 16 * LDROW) * 2);
        #pragma unroll
        for (int g = 0; g < 2; g++) {
            mma16816(acc[2 * g],     aH, bH[g]);
            mma16816(acc[2 * g + 1], aH, bH[g] + 2);
        }
        ldm_x4(aL, ALO + a_off + kb);
        #pragma unroll
        for (int g = 0; g < 2; g++) {
            mma16816(acc[2 * g],     aL, bH[g]);
            mma16816(acc[2 * g + 1], aL, bH[g] + 2);
        }
        #pragma unroll
        for (int g = 0; g < 2; g++)
            ldm_x4(bL[g], BLO + b_off + kb + (uint32_t)(g * 16 * LDROW) * 2);
        #pragma unroll
        for (int g = 0; g < 2; g++) {
            mma16816(acc[2 * g],     aH, bL[g]);
            mma16816(acc[2 * g + 1], aH, bL[g] + 2);
        }
    }
}

__device__ __forceinline__ void load_B_async(uint32_t sbase, uint32_t bhi_e, uint32_t blo_e,
                                             int tid,
                                             const __nv_bfloat16* Bhi, const __nv_bfloat16* Blo)
{
    #pragma unroll
    for (int c = 0; c < 2048; c += 256) {
        const int cc = c + tid;
        const int r = cc >> 4, col = (cc & 15) * 8;
        cp16(sbase + (bhi_e + (uint32_t)(r * LDROW + col)) * 2, Bhi + r * 128 + col);
        cp16(sbase + (blo_e + (uint32_t)(r * LDROW + col)) * 2, Blo + r * 128 + col);
    }
}

// ---------------------------------------------------------------------------
// Persistent QKV projection: loads fp32 x directly (register prefetch),
// converts to hi/lo smem in-register. grid=(99,3). Head-major outputs; Q*0.5.
// ---------------------------------------------------------------------------
__global__ __launch_bounds__(256, 2) void qkv_tc(
    const float* __restrict__ x,
    const float* __restrict__ bq, const float* __restrict__ bk,
    const float* __restrict__ bv, int Nn, int ntiles)
{
    extern __shared__ __nv_bfloat16 sm[];
    const uint32_t sbase = smem_u32(sm);
    const int tid = threadIdx.x;
    const int lane = tid & 31;
    const int w = tid >> 5;
    const int warp_m = w & 1;
    const int warp_n = w >> 1;
    const int o = blockIdx.y;

    float* dst = (o == 0) ? g_Q : (o == 1) ? g_K : g_V;
    const float alpha = (o == 0) ? 0.5f : 1.0f;
    const float* bias = (o == 0) ? bq : (o == 1) ? bk : bv;

    // hoisted epilogue constants (fixed per thread)
    int p0c[4], p1c[4];
    float b0c[4], b1c[4];
    #pragma unroll
    for (int nb = 0; nb < 4; nb++) {
        const int f0 = warp_n * 32 + nb * 8 + (lane & 3) * 2;
        const int f1 = f0 + 1;
        p0c[nb] = (f0 & 3) * 32 + (f0 >> 2);
        p1c[nb] = (f1 & 3) * 32 + (f1 >> 2);
        b0c[nb] = __ldg(&bias[f0]);
        b1c[nb] = __ldg(&bias[f1]);
    }

    load_B_async(sbase, QKV_B_HI, QKV_B_LO, tid, g_Whi + o * 16384, g_Wlo + o * 16384);
    CP_COMMIT();

    // A-loader mapping: 8 threads per row, 16 floats each
    const int arow = tid >> 3;
    const int acol = (tid & 7) * 16;

    int t = blockIdx.x;
    float4 r[4];
    if (t < ntiles) {
        const int m = t * A_ROWS + arow;
        const float* src = x + (size_t)m * 128 + acol;
        const bool v = m < Nn;
        #pragma unroll
        for (int i = 0; i < 4; i++)
            r[i] = v ? *(const float4*)(src + i * 4) : make_float4(0.f, 0.f, 0.f, 0.f);
    }
    CP_WAIT0();
    __syncthreads();   // B resident

    for (; t < ntiles; t += gridDim.x) {
        // convert prefetched regs -> A hi/lo smem
        #pragma unroll
        for (int i = 0; i < 4; i++) {
            const uint32_t e = (uint32_t)(arow * LDROW + acol + i * 4);
            split4(r[i],
                   (__nv_bfloat162*)&sm[e], (__nv_bfloat162*)&sm[e + 2],
                   (__nv_bfloat162*)&sm[QKV_A_PART + e], (__nv_bfloat162*)&sm[QKV_A_PART + e + 2]);
        }
        // prefetch next tile
        const int tn = t + gridDim.x;
        float4 rn[4];
        if (tn < ntiles) {
            const int m = tn * A_ROWS + arow;
            const float* src = x + (size_t)m * 128 + acol;
            const bool v = m < Nn;
            #pragma unroll
            for (int i = 0; i < 4; i++)
                rn[i] = v ? *(const float4*)(src + i * 4) : make_float4(0.f, 0.f, 0.f, 0.f);
        }
        __syncthreads();   // A hi/lo visible

        float acc[4][4];
        #pragma unroll
        for (int nb = 0; nb < 4; nb++)
            #pragma unroll
            for (int j = 0; j < 4; j++) acc[nb][j] = 0.f;

        mma_tile(acc, sbase, sbase + (uint32_t)QKV_A_PART * 2,
                 sbase + (uint32_t)QKV_B_HI * 2, sbase + (uint32_t)QKV_B_LO * 2,
                 warp_m, warp_n, lane);

        const int mrow = t * A_ROWS + warp_m * 16 + (lane >> 2);
        #pragma unroll
        for (int nb = 0; nb < 4; nb++) {
            if (mrow < Nn) {
                dst[(size_t)mrow * 128 + p0c[nb]] = (acc[nb][0] + b0c[nb]) * alpha;
                dst[(size_t)mrow * 128 + p1c[nb]] = (acc[nb][1] + b1c[nb]) * alpha;
            }
            if (mrow + 8 < Nn) {
                dst[(size_t)(mrow + 8) * 128 + p0c[nb]] = (acc[nb][2] + b0c[nb]) * alpha;
                dst[(size_t)(mrow + 8) * 128 + p1c[nb]] = (acc[nb][3] + b1c[nb]) * alpha;
            }
        }
        __syncthreads();   // all warps done with A before next convert
        #pragma unroll
        for (int i = 0; i < 4; i++) r[i] = rn[i];
    }
}

// ---------------------------------------------------------------------------
// Persistent output projection: A = Y hi/lo (bf16 from edge_attn), B = Wo.
// Double-buffered cp.async A tiles.
// ---------------------------------------------------------------------------
__device__ __forceinline__ void out_load_A(uint32_t sbase, int buf, int tid, int m0)
{
    const uint32_t abase = (uint32_t)(buf * OUT_A_BUF);
    #pragma unroll
    for (int c = 0; c < 512; c += 256) {
        const int cc = c + tid;
        const int r = cc >> 4, col = (cc & 15) * 8;
        cp16(sbase + (abase + (uint32_t)(r * LDROW + col)) * 2,
             g_Yhi + (size_t)(m0 + r) * 128 + col);
        cp16(sbase + (abase + (uint32_t)(OUT_A_PART + r * LDROW + col)) * 2,
             g_Ylo + (size_t)(m0 + r) * 128 + col);
    }
}

__global__ __launch_bounds__(256, 2) void out_tc(
    const float* __restrict__ bo, float* __restrict__ out, int Nn, int ntiles)
{
    extern __shared__ __nv_bfloat16 sm[];
    const uint32_t sbase = smem_u32(sm);
    const int tid = threadIdx.x;
    const int lane = tid & 31;
    const int w = tid >> 5;
    const int warp_m = w & 1;
    const int warp_n = w >> 1;

    float b0c[4], b1c[4];
    #pragma unroll
    for (int nb = 0; nb < 4; nb++) {
        const int f0 = warp_n * 32 + nb * 8 + (lane & 3) * 2;
        b0c[nb] = __ldg(&bo[f0]);
        b1c[nb] = __ldg(&bo[f0 + 1]);
    }

    load_B_async(sbase, OUT_B_HI, OUT_B_LO, tid, g_Whi + 3 * 16384, g_Wlo + 3 * 16384);
    int t = blockIdx.x;
    if (t < ntiles) out_load_A(sbase, 0, tid, t * A_ROWS);
    CP_COMMIT();

    int buf = 0;
    for (; t < ntiles; t += gridDim.x) {
        CP_WAIT0();
        __syncthreads();
        const int tn = t + gridDim.x;
        if (tn < ntiles) {
            out_load_A(sbase, buf ^ 1, tid, tn * A_ROWS);
            CP_COMMIT();
        }

        float acc[4][4];
        #pragma unroll
        for (int nb = 0; nb < 4; nb++)
            #pragma unroll
            for (int j = 0; j < 4; j++) acc[nb][j] = 0.f;

        const uint32_t AHI = sbase + (uint32_t)(buf * OUT_A_BUF) * 2;
        mma_tile(acc, AHI, AHI + (uint32_t)OUT_A_PART * 2,
                 sbase + (uint32_t)OUT_B_HI * 2, sbase + (uint32_t)OUT_B_LO * 2,
                 warp_m, warp_n, lane);

        const int mrow = t * A_ROWS + warp_m * 16 + (lane >> 2);
        #pragma unroll
        for (int nb = 0; nb < 4; nb++) {
            const int f0 = warp_n * 32 + nb * 8 + (lane & 3) * 2;
            if (mrow < Nn) {
                float2 v = make_float2(acc[nb][0] + b0c[nb], acc[nb][1] + b1c[nb]);
                *(float2*)&out[(size_t)mrow * 128 + f0] = v;
            }
            if (mrow + 8 < Nn) {
                float2 v = make_float2(acc[nb][2] + b0c[nb], acc[nb][3] + b1c[nb]);
                *(float2*)&out[(size_t)(mrow + 8) * 128 + f0] = v;
            }
        }
        buf ^= 1;
    }
}

// ---------------------------------------------------------------------------
// Fused edge attention: warp per node; cols loaded cooperatively (1 coalesced
// load per <=32-edge chunk, shfl broadcast); no max-subtract; unroll 4.
// ---------------------------------------------------------------------------
__global__ __launch_bounds__(256) void edge_attn(const int* __restrict__ col, int Nn)
{
    const int i = (blockIdx.x * blockDim.x + threadIdx.x) >> 5;
    const int lane = threadIdx.x & 31;
    if (i >= Nn) return;

    const int start = g_rowptr[i];
    const int end   = g_rowptr[i + 1];

    const float4 qv = *(const float4*)&g_Q[(size_t)i * 128 + lane * 4];

    float l = 0.f;
    float4 acc = make_float4(0.f, 0.f, 0.f, 0.f);

    for (int e = start; e < end; e += 32) {
        const int n = min(32, end - e);
        const int myc = (lane < n) ? __ldg(&col[e + lane]) : 0;

        int j = 0;
        for (; j + 4 <= n; j += 4) {
            const int c0 = __shfl_sync(0xffffffffu, myc, j);
            const int c1 = __shfl_sync(0xffffffffu, myc, j + 1);
            const int c2 = __shfl_sync(0xffffffffu, myc, j + 2);
            const int c3 = __shfl_sync(0xffffffffu, myc, j + 3);
            const float4 k0 = *(const float4*)&g_K[(size_t)c0 * 128 + lane * 4];
            const float4 k1 = *(const float4*)&g_K[(size_t)c1 * 128 + lane * 4];
            const float4 k2 = *(const float4*)&g_K[(size_t)c2 * 128 + lane * 4];
            const float4 k3 = *(const float4*)&g_K[(size_t)c3 * 128 + lane * 4];
            const float4 v0 = *(const float4*)&g_V[(size_t)c0 * 128 + lane * 4];
            const float4 v1 = *(const float4*)&g_V[(size_t)c1 * 128 + lane * 4];
            const float4 v2 = *(const float4*)&g_V[(size_t)c2 * 128 + lane * 4];
            const float4 v3 = *(const float4*)&g_V[(size_t)c3 * 128 + lane * 4];

            float s0 = qv.x * k0.x + qv.y * k0.y + qv.z * k0.z + qv.w * k0.w;
            float s1 = qv.x * k1.x + qv.y * k1.y + qv.z * k1.z + qv.w * k1.w;
            float s2 = qv.x * k2.x + qv.y * k2.y + qv.z * k2.z + qv.w * k2.w;
            float s3 = qv.x * k3.x + qv.y * k3.y + qv.z * k3.z + qv.w * k3.w;
            s0 += __shfl_xor_sync(0xffffffffu, s0, 1);
            s1 += __shfl_xor_sync(0xffffffffu, s1, 1);
            s2 += __shfl_xor_sync(0xffffffffu, s2, 1);
            s3 += __shfl_xor_sync(0xffffffffu, s3, 1);
            s0 += __shfl_xor_sync(0xffffffffu, s0, 2);
            s1 += __shfl_xor_sync(0xffffffffu, s1, 2);
            s2 += __shfl_xor_sync(0xffffffffu, s2, 2);
            s3 += __shfl_xor_sync(0xffffffffu, s3, 2);
            s0 += __shfl_xor_sync(0xffffffffu, s0, 4);
            s1 += __shfl_xor_sync(0xffffffffu, s1, 4);
            s2 += __shfl_xor_sync(0xffffffffu, s2, 4);
            s3 += __shfl_xor_sync(0xffffffffu, s3, 4);

            const float w0 = __expf(s0);
            const float w1 = __expf(s1);
            const float w2 = __expf(s2);
            const float w3 = __expf(s3);
            l += (w0 + w1) + (w2 + w3);

            acc.x += w0 * v0.x + w1 * v1.x + w2 * v2.x + w3 * v3.x;
            acc.y += w0 * v0.y + w1 * v1.y + w2 * v2.y + w3 * v3.y;
            acc.z += w0 * v0.z + w1 * v1.z + w2 * v2.z + w3 * v3.z;
            acc.w += w0 * v0.w + w1 * v1.w + w2 * v2.w + w3 * v3.w;
        }
        for (; j < n; j++) {
            const int c = __shfl_sync(0xffffffffu, myc, j);
            const float4 kv = *(const float4*)&g_K[(size_t)c * 128 + lane * 4];
            const float4 vv = *(const float4*)&g_V[(size_t)c * 128 + lane * 4];
            float s = qv.x * kv.x + qv.y * kv.y + qv.z * kv.z + qv.w * kv.w;
            s += __shfl_xor_sync(0xffffffffu, s, 1);
            s += __shfl_xor_sync(0xffffffffu, s, 2);
            s += __shfl_xor_sync(0xffffffffu, s, 4);
            const float wgt = __expf(s);
            l += wgt;
            acc.x += wgt * vv.x;
            acc.y += wgt * vv.y;
            acc.z += wgt * vv.z;
            acc.w += wgt * vv.w;
        }
    }

    const float inv = (l > 0.f) ? (1.f / l) : 0.f;
    float4 o;
    o.x = acc.x * inv; o.y = acc.y * inv; o.z = acc.z * inv; o.w = acc.w * inv;

    __nv_bfloat162 hp0, hp1, lp0, lp1;
    split4(o, &hp0, &hp1, &lp0, &lp1);
    const size_t base = (size_t)i * 128 + lane * 4;
    *(__nv_bfloat162*)&g_Yhi[base]     = hp0;
    *(__nv_bfloat162*)&g_Yhi[base + 2] = hp1;
    *(__nv_bfloat162*)&g_Ylo[base]     = lp0;
    *(__nv_bfloat162*)&g_Ylo[base + 2] = lp1;
}

// ---------------------------------------------------------------------------
extern "C" void kernel_launch(void* const* d_in, const int* in_sizes, int n_in,
                              void* d_out, int out_size)
{
    const float* x  = (const float*)d_in[0];
    const int*   row = (const int*)d_in[1];
    const int*   col = (const int*)d_in[2];
    const float* Wq = (const float*)d_in[3];
    const float* bq = (const float*)d_in[4];
    const float* Wk = (const float*)d_in[5];
    const float* bk = (const float*)d_in[6];
    const float* Wv = (const float*)d_in[7];
    const float* bv = (const float*)d_in[8];
    const float* Wo = (const float*)d_in[9];
    const float* bo = (const float*)d_in[10];

    const int Nn = in_sizes[0] / 128;
    const int E  = in_sizes[1];
    const int ntiles = (Nn + A_ROWS - 1) / A_ROWS;

    cudaFuncSetAttribute(qkv_tc, cudaFuncAttributeMaxDynamicSharedMemorySize, QKV_SMEM_BYTES);
    cudaFuncSetAttribute(out_tc, cudaFuncAttributeMaxDynamicSharedMemorySize, OUT_SMEM_BYTES);

    convert_weights<<<256, 256>>>(Wq, Wk, Wv, Wo);
    build_rowptr<<<(E + 255) / 256, 256>>>(row, E, Nn);

    qkv_tc<<<dim3(99, 3), 256, QKV_SMEM_BYTES>>>(x, bq, bk, bv, Nn, ntiles);

    const int edge_blocks = (Nn * 32 + 255) / 256;
    edge_attn<<<edge_blocks, 256>>>(col, Nn);

    out_tc<<<dim3(296, 1), 256, OUT_SMEM_BYTES>>>(bo, (float*)d_out, Nn, ntiles);
}